// round 10
// baseline (speedup 1.0000x reference)
#include <cuda_runtime.h>

// GraphAttentionPooling: B=32, N=3072, F=256, P=3 -> S=1024, 32768 windows.
// R7 topology (best: 21.0us): persistent 444 blocks (3/SM) x 256 thr,
// depth-1 register double-buffer + registerless prefetch.global.L2 (PD=6).
// R10: transposed warp indexing (wid = warp_in_block * n_blocks + block_id)
// so the 800 "one extra iteration" warps spread evenly across all SMs.

#define F_DIM 256
#define P_DIM 3
#define NUM_SMS 148
#define BLOCKS_PER_SM 3
#define THREADS_PER_BLOCK 256
#define PD 6   // prefetch distance in grid-stride iterations

__device__ __forceinline__ float warp_reduce_sum(float v) {
    #pragma unroll
    for (int off = 16; off > 0; off >>= 1)
        v += __shfl_xor_sync(0xFFFFFFFFu, v, off);
    return v;
}

__device__ __forceinline__ float dot8(float4 a, float4 b, float4 wa, float4 wb) {
    float s = a.x * wa.x;
    s = fmaf(a.y, wa.y, s);
    s = fmaf(a.z, wa.z, s);
    s = fmaf(a.w, wa.w, s);
    s = fmaf(b.x, wb.x, s);
    s = fmaf(b.y, wb.y, s);
    s = fmaf(b.z, wb.z, s);
    s = fmaf(b.w, wb.w, s);
    return s;
}

__global__ void __launch_bounds__(THREADS_PER_BLOCK, BLOCKS_PER_SM)
gap_kernel(const float* __restrict__ x,
           const float* __restrict__ Ww,
           const float* __restrict__ Wb,
           float* __restrict__ out,
           int n_windows) {
    // Transposed warp numbering: heavy warps (extra iteration) spread across blocks.
    const int warp_in_block = threadIdx.x >> 5;
    const int warp_id = warp_in_block * gridDim.x + blockIdx.x;
    const int lane    = threadIdx.x & 31;
    const int n_warps = (int)((gridDim.x * blockDim.x) >> 5);

    const int fv = lane * 2;  // float4 index within a row (row = 64 float4)

    const float4* Wv = reinterpret_cast<const float4*>(Ww);
    const float4 wa = Wv[fv], wb = Wv[fv + 1];
    const float bias = Wb[0];

    const float4* xbase = reinterpret_cast<const float4*>(x);
    float4*       obase = reinterpret_cast<float4*>(out);

    int w = warp_id;
    if (w >= n_windows) return;

    // Prologue: L2-prefetch the first PD windows of this warp's stream.
    // Window = 3072 B = 24 lines; lanes 0..23 take one 128B line each.
    if (lane < 24) {
        #pragma unroll
        for (int d = 0; d < PD; d++) {
            long long wi = w + (long long)d * n_warps;
            if (wi < n_windows) {
                const char* p = (const char*)x + wi * 3072 + lane * 128;
                asm volatile("prefetch.global.L2 [%0];" :: "l"(p));
            }
        }
    }

    // Register prefetch of window 0 (window stride = 192 float4).
    const float4* xin0 = xbase + (long long)w * 192 + fv;
    float4 n0a = __ldcs(xin0 + 0 * 64), n0b = __ldcs(xin0 + 0 * 64 + 1);
    float4 n1a = __ldcs(xin0 + 1 * 64), n1b = __ldcs(xin0 + 1 * 64 + 1);
    float4 n2a = __ldcs(xin0 + 2 * 64), n2b = __ldcs(xin0 + 2 * 64 + 1);

    for (; w < n_windows; w += n_warps) {
        // L2-prefetch the window PD iterations ahead (registerless).
        {
            long long wp = w + (long long)PD * n_warps;
            if (wp < n_windows && lane < 24) {
                const char* p = (const char*)x + wp * 3072 + lane * 128;
                asm volatile("prefetch.global.L2 [%0];" :: "l"(p));
            }
        }

        // Current window = last register prefetch.
        float4 r0a = n0a, r0b = n0b;
        float4 r1a = n1a, r1b = n1b;
        float4 r2a = n2a, r2b = n2b;

        // Register prefetch of next window BEFORE the dependent compute chain.
        {
            int wn = w + n_warps;
            wn = (wn < n_windows) ? wn : w;  // last iter: reload self (L2 hit)
            const float4* nx = xbase + (long long)wn * 192 + fv;
            n0a = __ldcs(nx + 0 * 64); n0b = __ldcs(nx + 0 * 64 + 1);
            n1a = __ldcs(nx + 1 * 64); n1b = __ldcs(nx + 1 * 64 + 1);
            n2a = __ldcs(nx + 2 * 64); n2b = __ldcs(nx + 2 * 64 + 1);
        }

        // Scores: per-lane partials + butterfly reduce (3 independent chains).
        float s0 = warp_reduce_sum(dot8(r0a, r0b, wa, wb)) + bias;
        float s1 = warp_reduce_sum(dot8(r1a, r1b, wa, wb)) + bias;
        float s2 = warp_reduce_sum(dot8(r2a, r2b, wa, wb)) + bias;

        // Softmax over 3 scores.
        float m = fmaxf(s0, fmaxf(s1, s2));
        float e0 = __expf(s0 - m);
        float e1 = __expf(s1 - m);
        float e2 = __expf(s2 - m);
        float inv = 1.0f / (e0 + e1 + e2);
        float a0 = e0 * inv, a1 = e1 * inv, a2 = e2 * inv;

        // Weighted combine.
        float4 oa, ob;
        oa.x = fmaf(r2a.x, a2, fmaf(r1a.x, a1, r0a.x * a0));
        oa.y = fmaf(r2a.y, a2, fmaf(r1a.y, a1, r0a.y * a0));
        oa.z = fmaf(r2a.z, a2, fmaf(r1a.z, a1, r0a.z * a0));
        oa.w = fmaf(r2a.w, a2, fmaf(r1a.w, a1, r0a.w * a0));
        ob.x = fmaf(r2b.x, a2, fmaf(r1b.x, a1, r0b.x * a0));
        ob.y = fmaf(r2b.y, a2, fmaf(r1b.y, a1, r0b.y * a0));
        ob.z = fmaf(r2b.z, a2, fmaf(r1b.z, a1, r0b.z * a0));
        ob.w = fmaf(r2b.w, a2, fmaf(r1b.w, a1, r0b.w * a0));

        float4* o = obase + (long long)w * 64 + fv;
        __stcs(o,     oa);
        __stcs(o + 1, ob);
    }
}

extern "C" void kernel_launch(void* const* d_in, const int* in_sizes, int n_in,
                              void* d_out, int out_size) {
    const float* x  = (const float*)d_in[0];  // [32, 3072, 256]
    const float* Ww = (const float*)d_in[1];  // [256]
    const float* Wb = (const float*)d_in[2];  // [1]
    float* out = (float*)d_out;               // [32, 1024, 256, 1]

    const int n_windows = in_sizes[0] / (P_DIM * F_DIM);  // 32768
    const int blocks = NUM_SMS * BLOCKS_PER_SM;           // 444, exact-fit one wave

    gap_kernel<<<blocks, THREADS_PER_BLOCK>>>(x, Ww, Wb, out, n_windows);
}

// round 11
// speedup vs baseline: 1.0351x; 1.0351x over previous
#include <cuda_runtime.h>

// GraphAttentionPooling: B=32, N=3072, F=256, P=3 -> S=1024, 32768 windows.
// R7 core (best: 21.0us) with CHUNKED work assignment: warp k owns ~9-10
// CONSECUTIVE windows, so its prefetch+load stream is one contiguous
// ~28-30KB sweep (DRAM row / L2 sector friendly), instead of grid-stride
// jumps of ~10MB. Depth-1 register double-buffer + prefetch.global.L2 (PD=4).

#define F_DIM 256
#define P_DIM 3
#define NUM_SMS 148
#define BLOCKS_PER_SM 3
#define THREADS_PER_BLOCK 256
#define PD 4   // prefetch distance in windows (within own chunk)

__device__ __forceinline__ float warp_reduce_sum(float v) {
    #pragma unroll
    for (int off = 16; off > 0; off >>= 1)
        v += __shfl_xor_sync(0xFFFFFFFFu, v, off);
    return v;
}

__device__ __forceinline__ float dot8(float4 a, float4 b, float4 wa, float4 wb) {
    float s = a.x * wa.x;
    s = fmaf(a.y, wa.y, s);
    s = fmaf(a.z, wa.z, s);
    s = fmaf(a.w, wa.w, s);
    s = fmaf(b.x, wb.x, s);
    s = fmaf(b.y, wb.y, s);
    s = fmaf(b.z, wb.z, s);
    s = fmaf(b.w, wb.w, s);
    return s;
}

__global__ void __launch_bounds__(THREADS_PER_BLOCK, BLOCKS_PER_SM)
gap_kernel(const float* __restrict__ x,
           const float* __restrict__ Ww,
           const float* __restrict__ Wb,
           float* __restrict__ out,
           int n_windows) {
    const int warp_id = (blockIdx.x * blockDim.x + threadIdx.x) >> 5;
    const int lane    = threadIdx.x & 31;
    const int n_warps = (int)((gridDim.x * blockDim.x) >> 5);

    // Chunked assignment: q windows per warp, first r warps get one extra,
    // all chunks contiguous in window space.
    const int q = n_windows / n_warps;
    const int r = n_windows - q * n_warps;
    const int wstart = warp_id * q + (warp_id < r ? warp_id : r);
    const int wend   = wstart + q + (warp_id < r ? 1 : 0);
    if (wstart >= wend) return;

    const int fv = lane * 2;  // float4 index within a row (row = 64 float4)

    const float4* Wv = reinterpret_cast<const float4*>(Ww);
    const float4 wa = Wv[fv], wb = Wv[fv + 1];
    const float bias = Wb[0];

    const float4* xbase = reinterpret_cast<const float4*>(x);
    float4*       obase = reinterpret_cast<float4*>(out);

    // Prologue: L2-prefetch the first PD windows of this warp's chunk.
    // Window = 3072 B = 24 lines; lanes 0..23 take one 128B line each.
    if (lane < 24) {
        #pragma unroll
        for (int d = 0; d < PD; d++) {
            int wi = wstart + d;
            if (wi < wend) {
                const char* p = (const char*)x + (long long)wi * 3072 + lane * 128;
                asm volatile("prefetch.global.L2 [%0];" :: "l"(p));
            }
        }
    }

    // Register prefetch of the first window (window stride = 192 float4).
    const float4* xin0 = xbase + (long long)wstart * 192 + fv;
    float4 n0a = __ldcs(xin0 + 0 * 64), n0b = __ldcs(xin0 + 0 * 64 + 1);
    float4 n1a = __ldcs(xin0 + 1 * 64), n1b = __ldcs(xin0 + 1 * 64 + 1);
    float4 n2a = __ldcs(xin0 + 2 * 64), n2b = __ldcs(xin0 + 2 * 64 + 1);

    for (int w = wstart; w < wend; w++) {
        // L2-prefetch the window PD ahead within the chunk (registerless).
        {
            int wp = w + PD;
            if (wp < wend && lane < 24) {
                const char* p = (const char*)x + (long long)wp * 3072 + lane * 128;
                asm volatile("prefetch.global.L2 [%0];" :: "l"(p));
            }
        }

        // Current window = last register prefetch.
        float4 r0a = n0a, r0b = n0b;
        float4 r1a = n1a, r1b = n1b;
        float4 r2a = n2a, r2b = n2b;

        // Register prefetch of next (consecutive) window BEFORE the compute chain.
        {
            int wn = (w + 1 < wend) ? (w + 1) : w;  // last iter: reload self (L2 hit)
            const float4* nx = xbase + (long long)wn * 192 + fv;
            n0a = __ldcs(nx + 0 * 64); n0b = __ldcs(nx + 0 * 64 + 1);
            n1a = __ldcs(nx + 1 * 64); n1b = __ldcs(nx + 1 * 64 + 1);
            n2a = __ldcs(nx + 2 * 64); n2b = __ldcs(nx + 2 * 64 + 1);
        }

        // Scores: per-lane partials + butterfly reduce (3 independent chains).
        float s0 = warp_reduce_sum(dot8(r0a, r0b, wa, wb)) + bias;
        float s1 = warp_reduce_sum(dot8(r1a, r1b, wa, wb)) + bias;
        float s2 = warp_reduce_sum(dot8(r2a, r2b, wa, wb)) + bias;

        // Softmax over 3 scores.
        float m = fmaxf(s0, fmaxf(s1, s2));
        float e0 = __expf(s0 - m);
        float e1 = __expf(s1 - m);
        float e2 = __expf(s2 - m);
        float inv = 1.0f / (e0 + e1 + e2);
        float a0 = e0 * inv, a1 = e1 * inv, a2 = e2 * inv;

        // Weighted combine.
        float4 oa, ob;
        oa.x = fmaf(r2a.x, a2, fmaf(r1a.x, a1, r0a.x * a0));
        oa.y = fmaf(r2a.y, a2, fmaf(r1a.y, a1, r0a.y * a0));
        oa.z = fmaf(r2a.z, a2, fmaf(r1a.z, a1, r0a.z * a0));
        oa.w = fmaf(r2a.w, a2, fmaf(r1a.w, a1, r0a.w * a0));
        ob.x = fmaf(r2b.x, a2, fmaf(r1b.x, a1, r0b.x * a0));
        ob.y = fmaf(r2b.y, a2, fmaf(r1b.y, a1, r0b.y * a0));
        ob.z = fmaf(r2b.z, a2, fmaf(r1b.z, a1, r0b.z * a0));
        ob.w = fmaf(r2b.w, a2, fmaf(r1b.w, a1, r0b.w * a0));

        float4* o = obase + (long long)w * 64 + fv;
        __stcs(o,     oa);
        __stcs(o + 1, ob);
    }
}

extern "C" void kernel_launch(void* const* d_in, const int* in_sizes, int n_in,
                              void* d_out, int out_size) {
    const float* x  = (const float*)d_in[0];  // [32, 3072, 256]
    const float* Ww = (const float*)d_in[1];  // [256]
    const float* Wb = (const float*)d_in[2];  // [1]
    float* out = (float*)d_out;               // [32, 1024, 256, 1]

    const int n_windows = in_sizes[0] / (P_DIM * F_DIM);  // 32768
    const int blocks = NUM_SMS * BLOCKS_PER_SM;           // 444, exact-fit one wave

    gap_kernel<<<blocks, THREADS_PER_BLOCK>>>(x, Ww, Wb, out, n_windows);
}